// round 1
// baseline (speedup 1.0000x reference)
#include <cuda_runtime.h>
#include <cuda_bf16.h>

#define W_IN 160
#define H_IN 160
#define C_IN 256
#define POOLED 7
#define SAMP 4
#define TILE 6
#define CSTRIDE 37   // TILE*TILE + 1 pad -> odd stride, conflict-free LDS across channels

__global__ __launch_bounds__(C_IN, 4)
void dcnv2_pool_kernel(const float* __restrict__ inp,
                       const float* __restrict__ rois,
                       const float* __restrict__ offset,
                       float* __restrict__ out,
                       int N)
{
    __shared__ float tile[C_IN * CSTRIDE];   // 37,888 B

    const int bin = blockIdx.x;          // 0..48
    const int n   = blockIdx.y;          // roi index
    const int ph  = bin / POOLED;
    const int pw  = bin % POOLED;
    const int c   = threadIdx.x;         // channel 0..255

    // ---- ROI parameters (identical across all threads; cheap, cached) ----
    const float* roi = rois + n * 5;
    const int   b  = (int)__ldg(&roi[0]);
    const float x1 = __ldg(&roi[1]);
    const float y1 = __ldg(&roi[2]);
    const float x2 = __ldg(&roi[3]);
    const float y2 = __ldg(&roi[4]);

    const float scale = 0.0625f;
    const float rsw = rintf(x1) * scale - 0.5f;             // jnp.round == rintf (RNE)
    const float rsh = rintf(y1) * scale - 0.5f;
    const float rew = (rintf(x2) + 1.0f) * scale - 0.5f;
    const float reh = (rintf(y2) + 1.0f) * scale - 0.5f;
    const float rw  = fmaxf(rew - rsw, 0.1f);
    const float rh  = fmaxf(reh - rsh, 0.1f);
    const float bw  = rw * (1.0f / 7.0f);
    const float bh  = rh * (1.0f / 7.0f);
    const float sw  = bw * 0.25f;
    const float sh  = bh * 0.25f;

    // part_h == ph, part_w == pw because PART == POOLED == 7
    const float tx = __ldg(&offset[((n * 2 + 0) * POOLED + ph) * POOLED + pw]) * 0.1f;
    const float ty = __ldg(&offset[((n * 2 + 1) * POOLED + ph) * POOLED + pw]) * 0.1f;

    const float wstart = pw * bw + rsw + tx * rw;
    const float hstart = ph * bh + rsh + ty * rh;

    // ---- tile origin: all 16 samples' bilinear footprint fits in [t0, t0+4] ----
    // sample span = 3*sw <= 2.16 px, so floor(min)..ceil(max) covers <= 5 ints.
    const float cxmin = fminf(fmaxf(wstart, 0.0f), (float)(W_IN - 1));
    const float cymin = fminf(fmaxf(hstart, 0.0f), (float)(H_IN - 1));
    const int tx0 = (int)floorf(cxmin);
    const int ty0 = (int)floorf(cymin);

    // ---- stage 6x6 footprint for all channels into shared ----
    const float* img = inp + (size_t)b * C_IN * (H_IN * W_IN);
    #pragma unroll
    for (int i = 0; i < TILE * TILE; i++) {
        // thread t handles channel t, element i  (contiguous x within a row -> sector-efficient)
        const int yy = i / TILE;
        const int xx = i % TILE;
        const int gy = min(ty0 + yy, H_IN - 1);
        const int gx = min(tx0 + xx, W_IN - 1);
        tile[c * CSTRIDE + i] = __ldg(&img[(size_t)c * (H_IN * W_IN) + gy * W_IN + gx]);
    }
    __syncthreads();

    // ---- 16-sample bilinear accumulation from shared ----
    const float* tch = tile + c * CSTRIDE;
    float sum = 0.0f;
    float cnt = 0.0f;

    #pragma unroll
    for (int iy = 0; iy < SAMP; iy++) {
        const float y  = hstart + (float)iy * sh;
        const bool  okY = (y >= -0.5f) && (y <= (float)H_IN - 0.5f);
        const float yc  = fminf(fmaxf(y, 0.0f), (float)(H_IN - 1));
        const float y0f = floorf(yc);
        const float y1f = ceilf(yc);
        const float dy  = yc - y0f;
        const int ry0 = (int)y0f - ty0;
        const int ry1 = (int)y1f - ty0;

        #pragma unroll
        for (int ix = 0; ix < SAMP; ix++) {
            const float x  = wstart + (float)ix * sw;
            const bool  ok = okY && (x >= -0.5f) && (x <= (float)W_IN - 0.5f);
            const float xc  = fminf(fmaxf(x, 0.0f), (float)(W_IN - 1));
            const float x0f = floorf(xc);
            const float x1f = ceilf(xc);
            const float dx  = xc - x0f;
            const int rx0 = (int)x0f - tx0;
            const int rx1 = (int)x1f - tx0;

            const float v00 = tch[ry0 * TILE + rx0];
            const float v01 = tch[ry1 * TILE + rx0];
            const float v10 = tch[ry0 * TILE + rx1];
            const float v11 = tch[ry1 * TILE + rx1];

            const float omdx = 1.0f - dx;
            const float omdy = 1.0f - dy;
            const float val = omdx * omdy * v00 + omdx * dy * v01
                            + dx   * omdy * v10 + dx   * dy * v11;
            if (ok) { sum += val; cnt += 1.0f; }
        }
    }

    out[(((size_t)n * C_IN + c) * POOLED + ph) * POOLED + pw] = sum / fmaxf(cnt, 1.0f);
}

extern "C" void kernel_launch(void* const* d_in, const int* in_sizes, int n_in,
                              void* d_out, int out_size)
{
    const float* inp    = (const float*)d_in[0];   // (2, 256, 160, 160) f32
    const float* rois   = (const float*)d_in[1];   // (N, 5) f32
    const float* offset = (const float*)d_in[2];   // (N, 2, 7, 7) f32
    float* out = (float*)d_out;                    // (N, 256, 7, 7) f32

    const int N = in_sizes[1] / 5;

    dim3 grid(POOLED * POOLED, N);                 // 49 x N blocks
    dim3 block(C_IN);                              // 256 threads = channels
    dcnv2_pool_kernel<<<grid, block>>>(inp, rois, offset, out, N);
}

// round 2
// speedup vs baseline: 3.2621x; 3.2621x over previous
#include <cuda_runtime.h>
#include <cuda_bf16.h>

#define W_IN 160
#define H_IN 160
#define C_IN 256
#define POOLED 7
#define SAMP 4
#define TILE 5
#define TSIZE (TILE * TILE)          // 25, odd -> conflict-free channel stride

__global__ __launch_bounds__(C_IN, 4)
void dcnv2_pool_kernel(const float* __restrict__ inp,
                       const float* __restrict__ rois,
                       const float* __restrict__ offset,
                       float* __restrict__ out,
                       int N)
{
    __shared__ float tile[C_IN * TSIZE];   // 25,600 B

    const int bin = blockIdx.x;          // 0..48
    const int n   = blockIdx.y;          // roi index
    const int ph  = bin / POOLED;
    const int pw  = bin % POOLED;
    const int tid = threadIdx.x;         // 0..255 (= channel in compute phase)

    // ---- ROI parameters (uniform across block) ----
    const float* roi = rois + n * 5;
    const int   b  = (int)__ldg(&roi[0]);
    const float x1 = __ldg(&roi[1]);
    const float y1 = __ldg(&roi[2]);
    const float x2 = __ldg(&roi[3]);
    const float y2 = __ldg(&roi[4]);

    const float scale = 0.0625f;
    const float rsw = rintf(x1) * scale - 0.5f;
    const float rsh = rintf(y1) * scale - 0.5f;
    const float rew = (rintf(x2) + 1.0f) * scale - 0.5f;
    const float reh = (rintf(y2) + 1.0f) * scale - 0.5f;
    const float rw  = fmaxf(rew - rsw, 0.1f);
    const float rh  = fmaxf(reh - rsh, 0.1f);
    const float bw  = rw * (1.0f / 7.0f);
    const float bh  = rh * (1.0f / 7.0f);
    const float sw  = bw * 0.25f;
    const float sh  = bh * 0.25f;

    // part_h == ph, part_w == pw because PART == POOLED == 7
    const float tx = __ldg(&offset[((n * 2 + 0) * POOLED + ph) * POOLED + pw]) * 0.1f;
    const float ty = __ldg(&offset[((n * 2 + 1) * POOLED + ph) * POOLED + pw]) * 0.1f;

    const float wstart = pw * bw + rsw + tx * rw;
    const float hstart = ph * bh + rsh + ty * rh;

    // ---- tile origin: footprint of all 16 samples fits in [t0, t0+4] ----
    // sample span = 3*sw <= 2.16 px  =>  ceil(max)-floor(min) <= 4  => 5x5 tile.
    const int tx0 = (int)floorf(fminf(fmaxf(wstart, 0.0f), (float)(W_IN - 1)));
    const int ty0 = (int)floorf(fminf(fmaxf(hstart, 0.0f), (float)(H_IN - 1)));

    // ---- stage 5x5 footprint for all 256 channels into shared ----
    // Flattened index so CONSECUTIVE LANES walk contiguous x within a channel
    // (coalesced), instead of striding across channels (32 wf per LDG).
    const float* img = inp + (size_t)b * C_IN * (H_IN * W_IN);
    #pragma unroll
    for (int i = 0; i < TSIZE; i++) {
        const int idx = i * C_IN + tid;          // 0..6399
        const int ch  = idx / TSIZE;             // 0..255
        const int e   = idx - ch * TSIZE;        // 0..24
        const int yy  = e / TILE;
        const int xx  = e - yy * TILE;
        const int gy  = min(ty0 + yy, H_IN - 1);
        const int gx  = min(tx0 + xx, W_IN - 1);
        tile[idx] = __ldg(&img[ch * (H_IN * W_IN) + gy * W_IN + gx]);
    }
    __syncthreads();

    // ---- 16-sample bilinear accumulation from shared (thread = channel) ----
    const float* tch = tile + tid * TSIZE;       // stride 25 words: conflict-free
    float sum = 0.0f;
    float cnt = 0.0f;

    #pragma unroll
    for (int iy = 0; iy < SAMP; iy++) {
        const float y   = hstart + (float)iy * sh;
        const bool  okY = (y >= -0.5f) && (y <= (float)H_IN - 0.5f);
        const float yc  = fminf(fmaxf(y, 0.0f), (float)(H_IN - 1));
        const float y0f = floorf(yc);
        const float dy  = yc - y0f;
        const int ry0 = (int)y0f - ty0;
        const int ry1 = (int)ceilf(yc) - ty0;

        #pragma unroll
        for (int ix = 0; ix < SAMP; ix++) {
            const float x  = wstart + (float)ix * sw;
            const bool  ok = okY && (x >= -0.5f) && (x <= (float)W_IN - 0.5f);
            const float xc  = fminf(fmaxf(x, 0.0f), (float)(W_IN - 1));
            const float x0f = floorf(xc);
            const float dx  = xc - x0f;
            const int rx0 = (int)x0f - tx0;
            const int rx1 = (int)ceilf(xc) - tx0;

            const float v00 = tch[ry0 * TILE + rx0];
            const float v01 = tch[ry1 * TILE + rx0];
            const float v10 = tch[ry0 * TILE + rx1];
            const float v11 = tch[ry1 * TILE + rx1];

            const float omdx = 1.0f - dx;
            const float omdy = 1.0f - dy;
            const float val = omdx * omdy * v00 + omdx * dy * v01
                            + dx   * omdy * v10 + dx   * dy * v11;
            if (ok) { sum += val; cnt += 1.0f; }
        }
    }

    out[(((size_t)n * C_IN + tid) * POOLED + ph) * POOLED + pw] = sum / fmaxf(cnt, 1.0f);
}

extern "C" void kernel_launch(void* const* d_in, const int* in_sizes, int n_in,
                              void* d_out, int out_size)
{
    const float* inp    = (const float*)d_in[0];   // (2, 256, 160, 160) f32
    const float* rois   = (const float*)d_in[1];   // (N, 5) f32
    const float* offset = (const float*)d_in[2];   // (N, 2, 7, 7) f32
    float* out = (float*)d_out;                    // (N, 256, 7, 7) f32

    const int N = in_sizes[1] / 5;

    dim3 grid(POOLED * POOLED, N);                 // 49 x N blocks
    dim3 block(C_IN);                              // 256 threads
    dcnv2_pool_kernel<<<grid, block>>>(inp, rois, offset, out, N);
}

// round 3
// speedup vs baseline: 4.1665x; 1.2772x over previous
#include <cuda_runtime.h>
#include <cuda_bf16.h>

#define W_IN 160
#define H_IN 160
#define HW   (H_IN * W_IN)
#define C_IN 256
#define POOLED 7
#define SAMP 4
#define MAXT 5                     // max footprint side (3*sw <= 2.16 => <=5)
#define MAXSTRIDE 25               // max per-channel smem stride (odd)

__global__ __launch_bounds__(C_IN, 6)
void dcnv2_pool_kernel(const float* __restrict__ inp,
                       const float* __restrict__ rois,
                       const float* __restrict__ offset,
                       float* __restrict__ out,
                       int N)
{
    __shared__ float tile[C_IN * MAXSTRIDE];   // 25.6 KB
    __shared__ float wacc[MAXSTRIDE];          // accumulated bilinear weights
    __shared__ float cnt_s;

    const int bin = blockIdx.x;
    const int n   = blockIdx.y;
    const int ph  = bin / POOLED;
    const int pw  = bin % POOLED;
    const int tid = threadIdx.x;
    const int lane = tid & 31;
    const int warp = tid >> 5;

    // ---- ROI geometry (uniform; every thread computes — cheap) ----
    const float* roi = rois + n * 5;
    const int   b  = (int)__ldg(&roi[0]);
    const float rsw = rintf(__ldg(&roi[1])) * 0.0625f - 0.5f;
    const float rsh = rintf(__ldg(&roi[2])) * 0.0625f - 0.5f;
    const float rew = (rintf(__ldg(&roi[3])) + 1.0f) * 0.0625f - 0.5f;
    const float reh = (rintf(__ldg(&roi[4])) + 1.0f) * 0.0625f - 0.5f;
    const float rw  = fmaxf(rew - rsw, 0.1f);
    const float rh  = fmaxf(reh - rsh, 0.1f);
    const float bw  = rw * (1.0f / 7.0f);
    const float bh  = rh * (1.0f / 7.0f);
    const float sw  = bw * 0.25f;
    const float sh  = bh * 0.25f;

    const float tx = __ldg(&offset[((n * 2 + 0) * POOLED + ph) * POOLED + pw]) * 0.1f;
    const float ty = __ldg(&offset[((n * 2 + 1) * POOLED + ph) * POOLED + pw]) * 0.1f;

    const float wstart = pw * bw + rsw + tx * rw;
    const float hstart = ph * bh + rsh + ty * rh;

    // ---- exact footprint bounds (x,y monotone in sample index) ----
    const float xcA = fminf(fmaxf(wstart,                 0.0f), (float)(W_IN - 1));
    const float xcB = fminf(fmaxf(wstart + 3.0f * sw,     0.0f), (float)(W_IN - 1));
    const float ycA = fminf(fmaxf(hstart,                 0.0f), (float)(H_IN - 1));
    const float ycB = fminf(fmaxf(hstart + 3.0f * sh,     0.0f), (float)(H_IN - 1));
    const int xlo = (int)floorf(xcA);
    const int ylo = (int)floorf(ycA);
    const int w   = min((int)ceilf(xcB) - xlo + 1, MAXT);   // 1..5
    const int h   = min((int)ceilf(ycB) - ylo + 1, MAXT);   // 1..5
    const int area   = w * h;                                // <= 25
    const int stride = area | 1;                             // odd -> conflict-free

    // ---- warp 0: per-sample geometry -> accumulated weights (block-uniform) ----
    if (tid < 32) {
        if (tid < MAXSTRIDE) wacc[tid] = 0.0f;
        __syncwarp();
        bool ok = false;
        if (tid < 16) {
            const int iy = tid >> 2;
            const int ix = tid & 3;
            const float x = wstart + (float)ix * sw;
            const float y = hstart + (float)iy * sh;
            ok = (x >= -0.5f) && (x <= (float)W_IN - 0.5f) &&
                 (y >= -0.5f) && (y <= (float)H_IN - 0.5f);
            const float xc = fminf(fmaxf(x, 0.0f), (float)(W_IN - 1));
            const float yc = fminf(fmaxf(y, 0.0f), (float)(H_IN - 1));
            const float x0f = floorf(xc);
            const float y0f = floorf(yc);
            const float dx = xc - x0f;
            const float dy = yc - y0f;
            int rx0 = min(max((int)x0f      - xlo, 0), w - 1);
            int rx1 = min(max((int)ceilf(xc) - xlo, 0), w - 1);
            int ry0 = min(max((int)y0f      - ylo, 0), h - 1);
            int ry1 = min(max((int)ceilf(yc) - ylo, 0), h - 1);
            if (ok) {
                const float omdx = 1.0f - dx;
                const float omdy = 1.0f - dy;
                atomicAdd(&wacc[ry0 * w + rx0], omdx * omdy);
                atomicAdd(&wacc[ry1 * w + rx0], omdx * dy);
                atomicAdd(&wacc[ry0 * w + rx1], dx * omdy);
                atomicAdd(&wacc[ry1 * w + rx1], dx * dy);
            }
        }
        const unsigned bal = __ballot_sync(0xffffffffu, ok);
        if (tid == 0) cnt_s = (float)__popc(bal);
    }

    // ---- stage footprint: warp per channel-iteration, lane = tile element ----
    {
        const int ylane = lane / w;          // one runtime div per thread
        const int xlane = lane - ylane * w;
        const bool lactive = lane < area;
        const float* gptr = inp + (size_t)b * (C_IN * HW)
                          + (size_t)(warp * 32) * HW
                          + (ylo + ylane) * W_IN + (xlo + xlane);
        float* sptr = tile + (warp * 32) * stride + lane;
        if (lactive) {
            #pragma unroll 4
            for (int i = 0; i < 32; i++) {
                *sptr = __ldg(gptr);
                gptr += HW;
                sptr += stride;
            }
        }
    }
    __syncthreads();

    // ---- thread = channel: dot(tile_row, wacc) ----
    const float* tch = tile + tid * stride;
    float dot = 0.0f;
    for (int e = 0; e < area; e++)
        dot += wacc[e] * tch[e];             // wacc: broadcast LDS

    out[(((size_t)n * C_IN + tid) * POOLED + ph) * POOLED + pw] =
        dot / fmaxf(cnt_s, 1.0f);
}

extern "C" void kernel_launch(void* const* d_in, const int* in_sizes, int n_in,
                              void* d_out, int out_size)
{
    const float* inp    = (const float*)d_in[0];   // (2, 256, 160, 160) f32
    const float* rois   = (const float*)d_in[1];   // (N, 5) f32
    const float* offset = (const float*)d_in[2];   // (N, 2, 7, 7) f32
    float* out = (float*)d_out;                    // (N, 256, 7, 7) f32

    const int N = in_sizes[1] / 5;

    dim3 grid(POOLED * POOLED, N);                 // 49 x N
    dim3 block(C_IN);
    dcnv2_pool_kernel<<<grid, block>>>(inp, rois, offset, out, N);
}